// round 1
// baseline (speedup 1.0000x reference)
#include <cuda_runtime.h>
#include <math.h>

#define BB 32
#define PP 24564
#define TT 20
#define CC 81

#define THRESH_HI 0.5f
#define THRESH_LO 0.4f
#define ALPHA     0.25f
#define VAR0      0.1f
#define VAR1      0.2f

#define LOSS_WARPS 8                       // warps per block in loss kernel
#define NROWS     (BB * PP)                // 786048
#define NBLK      ((NROWS + LOSS_WARPS - 1) / LOSS_WARPS)   // 98256

// ---------------- device scratch (no allocations allowed) ----------------
__device__ unsigned long long g_best_prior[BB * TT];  // packed (iou_bits<<32)|(~p)
__device__ float g_bt_ov[NROWS];
__device__ int   g_bt_idx[NROWS];
__device__ float g_part_l[NBLK];
__device__ float g_part_c[NBLK];
__device__ int   g_part_n[NBLK];

// ---------------- kernel 0: init ----------------
__global__ void init_kernel() {
    for (int i = threadIdx.x; i < BB * TT; i += blockDim.x)
        g_best_prior[i] = 0ull;
}

// ---------------- kernel 1: jaccard + per-prior argmax over truths +
//                  per-truth argmax over priors (packed atomicMax) --------
__global__ void match_kernel(const float* __restrict__ priors,
                             const float* __restrict__ targets) {
    __shared__ float s_t[TT][4];
    __shared__ unsigned long long s_key[TT];
    const int b   = blockIdx.y;
    const int tid = threadIdx.x;

    if (tid < TT * 4) {
        int t = tid >> 2, k = tid & 3;
        s_t[t][k] = targets[(b * TT + t) * 5 + k];
    }
    if (tid < TT) s_key[tid] = 0ull;
    __syncthreads();

    const int p = blockIdx.x * blockDim.x + tid;
    float4 pr = make_float4(0.5f, 0.5f, 0.1f, 0.1f);   // dummy for tail lanes
    if (p < PP) pr = reinterpret_cast<const float4*>(priors)[p];

    const float ax1 = pr.x - pr.z * 0.5f, ay1 = pr.y - pr.w * 0.5f;
    const float ax2 = pr.x + pr.z * 0.5f, ay2 = pr.y + pr.w * 0.5f;
    const float areap = pr.z * pr.w;

    float best_ov = -1.0f;
    int   best_t  = 0;

    #pragma unroll
    for (int t = 0; t < TT; t++) {
        const float tx1 = s_t[t][0], ty1 = s_t[t][1];
        const float tx2 = s_t[t][2], ty2 = s_t[t][3];
        float iw = fminf(ax2, tx2) - fmaxf(ax1, tx1);
        float ih = fminf(ay2, ty2) - fmaxf(ay1, ty1);
        iw = fmaxf(iw, 0.0f); ih = fmaxf(ih, 0.0f);
        const float inter = iw * ih;
        const float areat = (tx2 - tx1) * (ty2 - ty1);
        const float iou   = inter / (areat + areap - inter);

        if (iou > best_ov) { best_ov = iou; best_t = t; }   // first-occurrence ties

        // packed key: higher iou wins; equal iou -> smaller prior index wins
        unsigned long long key = 0ull;
        if (p < PP)
            key = (((unsigned long long)__float_as_uint(iou)) << 32)
                | (unsigned long long)(0xFFFFFFFFu - (unsigned)p);
        #pragma unroll
        for (int off = 16; off > 0; off >>= 1) {
            unsigned long long o = __shfl_down_sync(0xFFFFFFFFu, key, off);
            if (o > key) key = o;
        }
        if ((tid & 31) == 0) atomicMax(&s_key[t], key);
    }

    if (p < PP) {
        g_bt_ov [b * PP + p] = best_ov;
        g_bt_idx[b * PP + p] = best_t;
    }
    __syncthreads();
    if (tid < TT) atomicMax(&g_best_prior[b * TT + tid], s_key[tid]);
}

// ---------------- kernel 2: force match (sequential per batch -> last-wins) ----
__global__ void force_kernel() {
    const int b = threadIdx.x;
    if (b < BB) {
        for (int t = 0; t < TT; t++) {
            unsigned long long key = g_best_prior[b * TT + t];
            unsigned p = 0xFFFFFFFFu - (unsigned)(key & 0xFFFFFFFFull);
            g_bt_ov [b * PP + p] = 2.0f;
            g_bt_idx[b * PP + p] = t;
        }
    }
}

// ---------------- kernel 3: per-row focal + smooth-L1, block partials ---------
__global__ void loss_kernel(const float* __restrict__ loc,
                            const float* __restrict__ conf,
                            const float* __restrict__ priors,
                            const float* __restrict__ targets) {
    __shared__ float s_fl[LOSS_WARPS];
    __shared__ float s_ll[LOSS_WARPS];
    __shared__ int   s_np[LOSS_WARPS];

    const int wid  = threadIdx.x >> 5;
    const int lane = threadIdx.x & 31;
    const int row  = blockIdx.x * LOSS_WARPS + wid;

    float fl = 0.0f, ll = 0.0f;
    int   np = 0;

    if (row < NROWS) {
        const int b = row / PP;
        const int p = row - b * PP;

        const float ov  = g_bt_ov[row];
        const int   ti  = g_bt_idx[row];
        const float lab = targets[(b * TT + ti) * 5 + 4];
        int tgt = (int)lab + 1;
        if (ov < THRESH_HI) tgt = -1;
        if (ov < THRESH_LO) tgt = 0;

        if (tgt >= 0) {   // valid -> focal loss (warp-cooperative log-softmax)
            const float* base = conf + (size_t)row * CC;
            const float x0 = base[lane];
            const float x1 = base[lane + 32];
            const float x2 = (lane < CC - 64) ? base[lane + 64] : -1e30f;

            float m = fmaxf(fmaxf(x0, x1), x2);
            #pragma unroll
            for (int off = 16; off > 0; off >>= 1)
                m = fmaxf(m, __shfl_xor_sync(0xFFFFFFFFu, m, off));

            float s = __expf(x0 - m) + __expf(x1 - m)
                    + ((lane < CC - 64) ? __expf(x2 - m) : 0.0f);
            #pragma unroll
            for (int off = 16; off > 0; off >>= 1)
                s += __shfl_xor_sync(0xFFFFFFFFu, s, off);

            if (lane == 0) {
                const float lse   = m + __logf(s);
                const float xt    = base[tgt];
                const float logpt = xt - lse;
                const float pt    = __expf(logpt);
                const float at    = (tgt > 0) ? ALPHA : (1.0f - ALPHA);
                const float om    = 1.0f - pt;
                fl = -at * om * om * logpt;
            }
        }

        if (lane == 0 && tgt > 0) {   // positive -> localization smooth-L1
            np = 1;
            const float* tb = targets + (b * TT + ti) * 5;
            const float tx1 = tb[0], ty1 = tb[1], tx2 = tb[2], ty2 = tb[3];
            const float4 pr = reinterpret_cast<const float4*>(priors)[p];

            const float gcx = ((tx1 + tx2) * 0.5f - pr.x) / (VAR0 * pr.z);
            const float gcy = ((ty1 + ty2) * 0.5f - pr.y) / (VAR0 * pr.w);
            const float gw  = __logf((tx2 - tx1) / pr.z) / VAR1;
            const float gh  = __logf((ty2 - ty1) / pr.w) / VAR1;

            const float4 ld = reinterpret_cast<const float4*>(loc)[row];
            const float d0 = ld.x - gcx, d1 = ld.y - gcy;
            const float d2 = ld.z - gw,  d3 = ld.w - gh;
            float sl = 0.0f;
            {
                float ad;
                ad = fabsf(d0); sl += (ad < 1.0f) ? 0.5f * d0 * d0 : ad - 0.5f;
                ad = fabsf(d1); sl += (ad < 1.0f) ? 0.5f * d1 * d1 : ad - 0.5f;
                ad = fabsf(d2); sl += (ad < 1.0f) ? 0.5f * d2 * d2 : ad - 0.5f;
                ad = fabsf(d3); sl += (ad < 1.0f) ? 0.5f * d3 * d3 : ad - 0.5f;
            }
            ll = sl;
        }
    }

    if (lane == 0) { s_fl[wid] = fl; s_ll[wid] = ll; s_np[wid] = np; }
    __syncthreads();
    if (threadIdx.x == 0) {
        float tc = 0.0f, tl = 0.0f; int tn = 0;
        #pragma unroll
        for (int i = 0; i < LOSS_WARPS; i++) { tc += s_fl[i]; tl += s_ll[i]; tn += s_np[i]; }
        g_part_c[blockIdx.x] = tc;
        g_part_l[blockIdx.x] = tl;
        g_part_n[blockIdx.x] = tn;
    }
}

// ---------------- kernel 4: deterministic final reduction ----------------
__global__ void final_kernel(float* __restrict__ out) {
    __shared__ double s_l[1024];
    __shared__ double s_c[1024];
    __shared__ int    s_n[1024];
    const int tid = threadIdx.x;
    double tl = 0.0, tc = 0.0; int tn = 0;
    for (int i = tid; i < NBLK; i += 1024) {
        tl += (double)g_part_l[i];
        tc += (double)g_part_c[i];
        tn += g_part_n[i];
    }
    s_l[tid] = tl; s_c[tid] = tc; s_n[tid] = tn;
    __syncthreads();
    for (int off = 512; off > 0; off >>= 1) {
        if (tid < off) {
            s_l[tid] += s_l[tid + off];
            s_c[tid] += s_c[tid + off];
            s_n[tid] += s_n[tid + off];
        }
        __syncthreads();
    }
    if (tid == 0) {
        const double n = (double)s_n[0];
        out[0] = (float)(s_l[0] / n);
        out[1] = (float)(s_c[0] / n);
    }
}

// ---------------- launch ----------------
extern "C" void kernel_launch(void* const* d_in, const int* in_sizes, int n_in,
                              void* d_out, int out_size) {
    const float* loc     = (const float*)d_in[0];   // (B,P,4)
    const float* conf    = (const float*)d_in[1];   // (B,P,81)
    const float* priors  = (const float*)d_in[2];   // (P,4)
    const float* targets = (const float*)d_in[3];   // (B,T,5)
    float* out = (float*)d_out;

    init_kernel<<<1, 256>>>();

    dim3 g1((PP + 255) / 256, BB);
    match_kernel<<<g1, 256>>>(priors, targets);

    force_kernel<<<1, 32>>>();

    loss_kernel<<<NBLK, LOSS_WARPS * 32>>>(loc, conf, priors, targets);

    final_kernel<<<1, 1024>>>(out);
}

// round 3
// speedup vs baseline: 1.7772x; 1.7772x over previous
#include <cuda_runtime.h>
#include <math.h>

#define BB 32
#define PP 24564
#define TT 20
#define CC 81

#define THRESH_HI 0.5f
#define THRESH_LO 0.4f
#define ALPHA     0.25f
#define VAR0      0.1f
#define VAR1      0.2f

#define NROWS   (BB * PP)            // 786048
#define RPW     4                    // rows per warp
#define WPB     8                    // warps per block
#define RPB     (RPW * WPB)          // 32 rows per block
#define NBLK2   (NROWS / RPB)        // 24564 (exact)

// ---------------- device scratch (no allocations allowed) ----------------
__device__ unsigned long long g_best_prior[BB * TT]; // packed (iou_bits<<32)|(~p)
__device__ int   g_tgt[NROWS];       // packed: (tgt+1) in [0..82] low 8 bits | ti<<8
__device__ float g_part_l[NBLK2];
__device__ float g_part_c[NBLK2];
__device__ int   g_part_n[NBLK2];

// ---------------- kernel 0: init ----------------
__global__ void init_kernel() {
    for (int i = threadIdx.x; i < BB * TT; i += blockDim.x)
        g_best_prior[i] = 0ull;
}

// ---- kernel 1: jaccard; per-prior argmax over truths -> packed tgt;
//      per-truth argmax over priors via REDUX + packed atomicMax ----------
__global__ void match_kernel(const float* __restrict__ priors,
                             const float* __restrict__ targets) {
    __shared__ float s_t[TT][4];
    __shared__ float s_lab[TT];
    __shared__ unsigned long long s_key[TT];
    const int b   = blockIdx.y;
    const int tid = threadIdx.x;

    if (tid < TT) {
        const float* tb = targets + (b * TT + tid) * 5;
        s_t[tid][0] = tb[0]; s_t[tid][1] = tb[1];
        s_t[tid][2] = tb[2]; s_t[tid][3] = tb[3];
        s_lab[tid]  = tb[4];
        s_key[tid]  = 0ull;
    }
    __syncthreads();

    const int p = blockIdx.x * blockDim.x + tid;
    float4 pr = make_float4(0.5f, 0.5f, 0.1f, 0.1f);   // dummy for tail lanes
    if (p < PP) pr = reinterpret_cast<const float4*>(priors)[p];

    const float ax1 = pr.x - pr.z * 0.5f, ay1 = pr.y - pr.w * 0.5f;
    const float ax2 = pr.x + pr.z * 0.5f, ay2 = pr.y + pr.w * 0.5f;
    const float areap = pr.z * pr.w;

    float best_ov = -1.0f;
    int   best_t  = 0;

    #pragma unroll
    for (int t = 0; t < TT; t++) {
        const float tx1 = s_t[t][0], ty1 = s_t[t][1];
        const float tx2 = s_t[t][2], ty2 = s_t[t][3];
        float iw = fminf(ax2, tx2) - fmaxf(ax1, tx1);
        float ih = fminf(ay2, ty2) - fmaxf(ay1, ty1);
        iw = fmaxf(iw, 0.0f); ih = fmaxf(ih, 0.0f);
        const float inter = iw * ih;
        const float areat = (tx2 - tx1) * (ty2 - ty1);
        const float iou   = inter / (areat + areap - inter);

        if (iou > best_ov) { best_ov = iou; best_t = t; }  // first occurrence

        // warp max via REDUX (iou >= 0 so float bits are order-preserving)
        unsigned u = (p < PP) ? __float_as_uint(iou) : 0u;
        unsigned m = __reduce_max_sync(0xFFFFFFFFu, u);
        unsigned eq = __ballot_sync(0xFFFFFFFFu, u == m);
        if ((tid & 31) == (__ffs(eq) - 1)) {
            unsigned long long key = (((unsigned long long)m) << 32)
                                   | (unsigned long long)(0xFFFFFFFFu - (unsigned)p);
            atomicMax(&s_key[t], key);
        }
    }

    if (p < PP) {
        int tgt = (int)s_lab[best_t] + 1;
        if (best_ov < THRESH_HI) tgt = -1;
        if (best_ov < THRESH_LO) tgt = 0;
        g_tgt[b * PP + p] = ((tgt + 1) & 0xFF) | (best_t << 8);
    }
    __syncthreads();
    if (tid < TT) atomicMax(&g_best_prior[b * TT + tid], s_key[tid]);
}

// ---------------- kernel 2: force match (sequential per batch -> last-wins) ----
__global__ void force_kernel(const float* __restrict__ targets) {
    const int b = threadIdx.x;
    if (b < BB) {
        for (int t = 0; t < TT; t++) {
            unsigned long long key = g_best_prior[b * TT + t];
            unsigned p = 0xFFFFFFFFu - (unsigned)(key & 0xFFFFFFFFull);
            float lab = targets[(b * TT + t) * 5 + 4];
            // forced: overlap=2.0 -> tgt = lab+1 (always positive), ti = t
            g_tgt[b * PP + p] = (((int)lab + 2) & 0xFF) | (t << 8);
        }
    }
}

// ---------------- kernel 3: focal + smooth-L1, 4 rows per warp ----------------
__global__ void loss_kernel(const float* __restrict__ loc,
                            const float* __restrict__ conf,
                            const float* __restrict__ priors,
                            const float* __restrict__ targets) {
    __shared__ float s_fl[WPB];
    __shared__ float s_ll[WPB];
    __shared__ int   s_np[WPB];

    const int wid  = threadIdx.x >> 5;
    const int lane = threadIdx.x & 31;
    const int row0 = blockIdx.x * RPB + wid * RPW;

    // one uniform 16B load covers match state for all 4 rows
    const int4 pk = *reinterpret_cast<const int4*>(g_tgt + row0);
    int pkv[RPW] = { pk.x, pk.y, pk.z, pk.w };

    const float* base = conf + (size_t)row0 * CC;
    float x0[RPW], x1[RPW], x2[RPW], s[RPW];

    #pragma unroll
    for (int j = 0; j < RPW; j++) {
        const float* bp = base + j * CC;
        x0[j] = bp[lane];
        x1[j] = bp[lane + 32];
        x2[j] = (lane < CC - 64) ? bp[lane + 64] : 0.0f;
    }
    #pragma unroll
    for (int j = 0; j < RPW; j++) {
        s[j] = __expf(x0[j]) + __expf(x1[j])
             + ((lane < CC - 64) ? __expf(x2[j]) : 0.0f);
    }
    // 4 interleaved butterfly sum chains
    #pragma unroll
    for (int off = 16; off > 0; off >>= 1) {
        #pragma unroll
        for (int j = 0; j < RPW; j++)
            s[j] += __shfl_xor_sync(0xFFFFFFFFu, s[j], off);
    }

    float fl = 0.0f, ll = 0.0f;
    int   np = 0;

    #pragma unroll
    for (int j = 0; j < RPW; j++) {
        const int tg = (pkv[j] & 0xFF) - 1;       // -1, 0, or 1..80
        const int ts = (tg < 0) ? 0 : tg;
        const int sel = ts >> 5;                   // uniform per row
        const float v  = (sel == 0) ? x0[j] : ((sel == 1) ? x1[j] : x2[j]);
        const float xt = __shfl_sync(0xFFFFFFFFu, v, ts & 31);

        if (lane == 0 && tg >= 0) {
            const float lse   = __logf(s[j]);
            const float logpt = xt - lse;
            const float pt    = __expf(logpt);
            const float at    = (tg > 0) ? ALPHA : (1.0f - ALPHA);
            const float om    = 1.0f - pt;
            fl += -at * om * om * logpt;
        }

        if (tg > 0) {   // warp-uniform, rare: localization loss
            if (lane == 0) {
                np++;
                const int row = row0 + j;
                const int b = row / PP;
                const int p = row - b * PP;
                const int ti = (pkv[j] >> 8) & 0xFF;
                const float* tb = targets + (b * TT + ti) * 5;
                const float tx1 = tb[0], ty1 = tb[1], tx2 = tb[2], ty2 = tb[3];
                const float4 pr = reinterpret_cast<const float4*>(priors)[p];

                const float gcx = ((tx1 + tx2) * 0.5f - pr.x) / (VAR0 * pr.z);
                const float gcy = ((ty1 + ty2) * 0.5f - pr.y) / (VAR0 * pr.w);
                const float gw  = __logf((tx2 - tx1) / pr.z) / VAR1;
                const float gh  = __logf((ty2 - ty1) / pr.w) / VAR1;

                const float4 ld = reinterpret_cast<const float4*>(loc)[row];
                const float d0 = ld.x - gcx, d1 = ld.y - gcy;
                const float d2 = ld.z - gw,  d3 = ld.w - gh;
                float ad;
                ad = fabsf(d0); ll += (ad < 1.0f) ? 0.5f * d0 * d0 : ad - 0.5f;
                ad = fabsf(d1); ll += (ad < 1.0f) ? 0.5f * d1 * d1 : ad - 0.5f;
                ad = fabsf(d2); ll += (ad < 1.0f) ? 0.5f * d2 * d2 : ad - 0.5f;
                ad = fabsf(d3); ll += (ad < 1.0f) ? 0.5f * d3 * d3 : ad - 0.5f;
            }
        }
    }

    if (lane == 0) { s_fl[wid] = fl; s_ll[wid] = ll; s_np[wid] = np; }
    __syncthreads();
    if (threadIdx.x == 0) {
        float tc = 0.0f, tl = 0.0f; int tn = 0;
        #pragma unroll
        for (int i = 0; i < WPB; i++) { tc += s_fl[i]; tl += s_ll[i]; tn += s_np[i]; }
        g_part_c[blockIdx.x] = tc;
        g_part_l[blockIdx.x] = tl;
        g_part_n[blockIdx.x] = tn;
    }
}

// ---------------- kernel 4: deterministic final reduction ----------------
__global__ void final_kernel(float* __restrict__ out) {
    __shared__ double s_l[1024];
    __shared__ double s_c[1024];
    __shared__ int    s_n[1024];
    const int tid = threadIdx.x;
    double tl = 0.0, tc = 0.0; int tn = 0;
    for (int i = tid; i < NBLK2; i += 1024) {
        tl += (double)g_part_l[i];
        tc += (double)g_part_c[i];
        tn += g_part_n[i];
    }
    s_l[tid] = tl; s_c[tid] = tc; s_n[tid] = tn;
    __syncthreads();
    for (int off = 512; off > 0; off >>= 1) {
        if (tid < off) {
            s_l[tid] += s_l[tid + off];
            s_c[tid] += s_c[tid + off];
            s_n[tid] += s_n[tid + off];
        }
        __syncthreads();
    }
    if (tid == 0) {
        const double n = (double)s_n[0];
        out[0] = (float)(s_l[0] / n);
        out[1] = (float)(s_c[0] / n);
    }
}

// ---------------- launch ----------------
extern "C" void kernel_launch(void* const* d_in, const int* in_sizes, int n_in,
                              void* d_out, int out_size) {
    const float* loc     = (const float*)d_in[0];   // (B,P,4)
    const float* conf    = (const float*)d_in[1];   // (B,P,81)
    const float* priors  = (const float*)d_in[2];   // (P,4)
    const float* targets = (const float*)d_in[3];   // (B,T,5)
    float* out = (float*)d_out;

    init_kernel<<<1, 256>>>();

    dim3 g1((PP + 255) / 256, BB);
    match_kernel<<<g1, 256>>>(priors, targets);

    force_kernel<<<1, 32>>>(targets);

    loss_kernel<<<NBLK2, WPB * 32>>>(loc, conf, priors, targets);

    final_kernel<<<1, 1024>>>(out);
}

// round 4
// speedup vs baseline: 2.8775x; 1.6192x over previous
#include <cuda_runtime.h>
#include <math.h>

#define BB 32
#define PP 24564
#define TT 20
#define CC 81

#define THRESH_HI 0.5f
#define THRESH_LO 0.4f
#define ALPHA     0.25f
#define VAR0      0.1f
#define VAR1      0.2f

#define NROWS    (BB * PP)           // 786048
#define RPB3     128                 // rows per block (= threads per block)
#define NBLK3    (NROWS / RPB3)      // 6141 (exact)
#define TILE_F4  ((RPB3 * CC) / 4)   // 2592 float4 per block tile

// ---------------- device scratch (no allocations allowed) ----------------
__device__ unsigned long long g_best_prior[BB * TT]; // packed (iou_bits<<32)|(~p)
__device__ int   g_tgt[NROWS];       // packed: (tgt+1) in [0..81] low 8 bits | ti<<8
__device__ float g_part_l[NBLK3];
__device__ float g_part_c[NBLK3];
__device__ int   g_part_n[NBLK3];

// ---------------- kernel 0: init ----------------
__global__ void init_kernel() {
    for (int i = threadIdx.x; i < BB * TT; i += blockDim.x)
        g_best_prior[i] = 0ull;
}

// ---- kernel 1: jaccard; per-prior argmax over truths -> packed tgt;
//      per-truth argmax over priors via REDUX + packed atomicMax ----------
__global__ void match_kernel(const float* __restrict__ priors,
                             const float* __restrict__ targets) {
    __shared__ float s_t[TT][4];
    __shared__ float s_lab[TT];
    __shared__ unsigned long long s_key[TT];
    const int b   = blockIdx.y;
    const int tid = threadIdx.x;

    if (tid < TT) {
        const float* tb = targets + (b * TT + tid) * 5;
        s_t[tid][0] = tb[0]; s_t[tid][1] = tb[1];
        s_t[tid][2] = tb[2]; s_t[tid][3] = tb[3];
        s_lab[tid]  = tb[4];
        s_key[tid]  = 0ull;
    }
    __syncthreads();

    const int p = blockIdx.x * blockDim.x + tid;
    float4 pr = make_float4(0.5f, 0.5f, 0.1f, 0.1f);   // dummy for tail lanes
    if (p < PP) pr = reinterpret_cast<const float4*>(priors)[p];

    const float ax1 = pr.x - pr.z * 0.5f, ay1 = pr.y - pr.w * 0.5f;
    const float ax2 = pr.x + pr.z * 0.5f, ay2 = pr.y + pr.w * 0.5f;
    const float areap = pr.z * pr.w;

    float best_ov = -1.0f;
    int   best_t  = 0;

    #pragma unroll
    for (int t = 0; t < TT; t++) {
        const float tx1 = s_t[t][0], ty1 = s_t[t][1];
        const float tx2 = s_t[t][2], ty2 = s_t[t][3];
        float iw = fminf(ax2, tx2) - fmaxf(ax1, tx1);
        float ih = fminf(ay2, ty2) - fmaxf(ay1, ty1);
        iw = fmaxf(iw, 0.0f); ih = fmaxf(ih, 0.0f);
        const float inter = iw * ih;
        const float areat = (tx2 - tx1) * (ty2 - ty1);
        const float iou   = __fdividef(inter, areat + areap - inter);

        if (iou > best_ov) { best_ov = iou; best_t = t; }  // first occurrence

        // warp max via REDUX (iou >= 0 so float bits are order-preserving)
        unsigned u = (p < PP) ? __float_as_uint(iou) : 0u;
        unsigned m = __reduce_max_sync(0xFFFFFFFFu, u);
        unsigned eq = __ballot_sync(0xFFFFFFFFu, u == m);
        if ((tid & 31) == (__ffs(eq) - 1)) {
            unsigned long long key = (((unsigned long long)m) << 32)
                                   | (unsigned long long)(0xFFFFFFFFu - (unsigned)p);
            atomicMax(&s_key[t], key);
        }
    }

    if (p < PP) {
        int tgt = (int)s_lab[best_t] + 1;
        if (best_ov < THRESH_HI) tgt = -1;
        if (best_ov < THRESH_LO) tgt = 0;
        g_tgt[b * PP + p] = ((tgt + 1) & 0xFF) | (best_t << 8);
    }
    __syncthreads();
    if (tid < TT) atomicMax(&g_best_prior[b * TT + tid], s_key[tid]);
}

// ---------------- kernel 2: force match (sequential per batch -> last-wins) ----
__global__ void force_kernel(const float* __restrict__ targets) {
    const int b = threadIdx.x;
    if (b < BB) {
        for (int t = 0; t < TT; t++) {
            unsigned long long key = g_best_prior[b * TT + t];
            unsigned p = 0xFFFFFFFFu - (unsigned)(key & 0xFFFFFFFFull);
            float lab = targets[(b * TT + t) * 5 + 4];
            // forced: overlap=2.0 -> tgt = lab+1 (always positive), ti = t
            g_tgt[b * PP + p] = (((int)lab + 2) & 0xFF) | (t << 8);
        }
    }
}

// ------- kernel 3: focal + smooth-L1, thread-per-row with smem staging -------
__global__ void __launch_bounds__(RPB3, 5)
loss_kernel(const float* __restrict__ loc,
            const float* __restrict__ conf,
            const float* __restrict__ priors,
            const float* __restrict__ targets) {
    __shared__ float tile[RPB3 * CC];           // 41472 B, row stride 81
    __shared__ float s_fl[RPB3 / 32];
    __shared__ float s_ll[RPB3 / 32];
    __shared__ int   s_np[RPB3 / 32];

    const int tid  = threadIdx.x;
    const int lane = tid & 31;
    const int wid  = tid >> 5;
    const int row0 = blockIdx.x * RPB3;
    const int row  = row0 + tid;

    // coalesced float4 stage: block tile is contiguous in gmem
    {
        const float4* src = reinterpret_cast<const float4*>(conf + (size_t)row0 * CC);
        float4* dst = reinterpret_cast<float4*>(tile);
        #pragma unroll
        for (int i = tid; i < TILE_F4; i += RPB3)
            dst[i] = src[i];
    }
    const int pk = g_tgt[row];                   // coalesced 4B per thread
    __syncthreads();

    // each thread owns one row: 81 conflict-free scalar LDS (17*lane+c mod 32)
    const float* myrow = tile + tid * CC;
    float sum = 0.0f;
    #pragma unroll 9
    for (int c = 0; c < CC; c++)
        sum += __expf(myrow[c]);

    const int tg = (pk & 0xFF) - 1;              // -1, 0, or 1..80
    float fl = 0.0f, ll = 0.0f;
    int   np = 0;

    if (tg >= 0) {                               // valid -> focal loss
        const float xt    = myrow[tg];
        const float lse   = __logf(sum);
        const float logpt = xt - lse;
        const float pt    = __expf(logpt);
        const float at    = (tg > 0) ? ALPHA : (1.0f - ALPHA);
        const float om    = 1.0f - pt;
        fl = -at * om * om * logpt;
    }

    if (tg > 0) {                                // positive (rare) -> smooth-L1
        np = 1;
        const int b  = row / PP;
        const int p  = row - b * PP;
        const int ti = (pk >> 8) & 0xFF;
        const float* tb = targets + (b * TT + ti) * 5;
        const float tx1 = tb[0], ty1 = tb[1], tx2 = tb[2], ty2 = tb[3];
        const float4 pr = reinterpret_cast<const float4*>(priors)[p];

        const float gcx = ((tx1 + tx2) * 0.5f - pr.x) / (VAR0 * pr.z);
        const float gcy = ((ty1 + ty2) * 0.5f - pr.y) / (VAR0 * pr.w);
        const float gw  = __logf((tx2 - tx1) / pr.z) / VAR1;
        const float gh  = __logf((ty2 - ty1) / pr.w) / VAR1;

        const float4 ld = reinterpret_cast<const float4*>(loc)[row];
        const float d0 = ld.x - gcx, d1 = ld.y - gcy;
        const float d2 = ld.z - gw,  d3 = ld.w - gh;
        float ad;
        ad = fabsf(d0); ll += (ad < 1.0f) ? 0.5f * d0 * d0 : ad - 0.5f;
        ad = fabsf(d1); ll += (ad < 1.0f) ? 0.5f * d1 * d1 : ad - 0.5f;
        ad = fabsf(d2); ll += (ad < 1.0f) ? 0.5f * d2 * d2 : ad - 0.5f;
        ad = fabsf(d3); ll += (ad < 1.0f) ? 0.5f * d3 * d3 : ad - 0.5f;
    }

    // warp butterfly, then cross-warp via smem
    #pragma unroll
    for (int off = 16; off > 0; off >>= 1) {
        fl += __shfl_xor_sync(0xFFFFFFFFu, fl, off);
        ll += __shfl_xor_sync(0xFFFFFFFFu, ll, off);
        np += __shfl_xor_sync(0xFFFFFFFFu, np, off);
    }
    if (lane == 0) { s_fl[wid] = fl; s_ll[wid] = ll; s_np[wid] = np; }
    __syncthreads();
    if (tid == 0) {
        float tc = 0.0f, tl = 0.0f; int tn = 0;
        #pragma unroll
        for (int i = 0; i < RPB3 / 32; i++) { tc += s_fl[i]; tl += s_ll[i]; tn += s_np[i]; }
        g_part_c[blockIdx.x] = tc;
        g_part_l[blockIdx.x] = tl;
        g_part_n[blockIdx.x] = tn;
    }
}

// ---------------- kernel 4: deterministic final reduction ----------------
__global__ void final_kernel(float* __restrict__ out) {
    __shared__ double s_l[1024];
    __shared__ double s_c[1024];
    __shared__ int    s_n[1024];
    const int tid = threadIdx.x;
    double tl = 0.0, tc = 0.0; int tn = 0;
    for (int i = tid; i < NBLK3; i += 1024) {
        tl += (double)g_part_l[i];
        tc += (double)g_part_c[i];
        tn += g_part_n[i];
    }
    s_l[tid] = tl; s_c[tid] = tc; s_n[tid] = tn;
    __syncthreads();
    for (int off = 512; off > 0; off >>= 1) {
        if (tid < off) {
            s_l[tid] += s_l[tid + off];
            s_c[tid] += s_c[tid + off];
            s_n[tid] += s_n[tid + off];
        }
        __syncthreads();
    }
    if (tid == 0) {
        const double n = (double)s_n[0];
        out[0] = (float)(s_l[0] / n);
        out[1] = (float)(s_c[0] / n);
    }
}

// ---------------- launch ----------------
extern "C" void kernel_launch(void* const* d_in, const int* in_sizes, int n_in,
                              void* d_out, int out_size) {
    const float* loc     = (const float*)d_in[0];   // (B,P,4)
    const float* conf    = (const float*)d_in[1];   // (B,P,81)
    const float* priors  = (const float*)d_in[2];   // (P,4)
    const float* targets = (const float*)d_in[3];   // (B,T,5)
    float* out = (float*)d_out;

    init_kernel<<<1, 256>>>();

    dim3 g1((PP + 255) / 256, BB);
    match_kernel<<<g1, 256>>>(priors, targets);

    force_kernel<<<1, 32>>>(targets);

    loss_kernel<<<NBLK3, RPB3>>>(loc, conf, priors, targets);

    final_kernel<<<1, 1024>>>(out);
}